// round 4
// baseline (speedup 1.0000x reference)
#include <cuda_runtime.h>
#include <cstdint>

// Cost volume, B=8 C=128 H=128 W=256, d=4 -> 81 shifts.
// out[b, i*9+j, h, w] = (1/C) * sum_c f1[b,c,h,w] * f2[b,c,h+i-4,w+j-4] (zero pad)
//
// v3: packed fp32 (fma.rn.f32x2), column-major smem tile (vertical pairs via
// LDS.64), 4 vertical pixels per thread, 81 shifts split j=[0,5)/[5,9) across
// two 128-thread groups sharing the tile. Group B also streams f2 -> smem.

typedef unsigned long long ull;

namespace {
constexpr int Bc = 8;
constexpr int Cc = 128;
constexpr int Hc = 128;
constexpr int Wc = 256;
constexpr int Dd = 4;
constexpr int Ss = 9;
constexpr int NS = 81;
constexpr int TH = 16;             // tile rows
constexpr int TW = 32;             // tile cols
constexpr int F2H = TH + 2 * Dd;   // 24
constexpr int F2W = TW + 2 * Dd;   // 40
constexpr int CST = 26;            // padded column stride (floats), even
constexpr int SBUF = F2W * CST;    // 1040 floats per buffer
constexpr int HW = Hc * Wc;
constexpr int NLOAD = F2H * (F2W / 4);  // 240 float4 loads per channel tile
}

__device__ __forceinline__ void fma2(ull& acc, ull a, ull b) {
    asm("fma.rn.f32x2 %0, %1, %2, %0;" : "+l"(acc) : "l"(a), "l"(b));
}
__device__ __forceinline__ ull packf(float lo, float hi) {
    ull r; asm("mov.b64 %0, {%1, %2};" : "=l"(r) : "f"(lo), "f"(hi)); return r;
}
__device__ __forceinline__ ull packu(unsigned lo, unsigned hi) {
    ull r; asm("mov.b64 %0, {%1, %2};" : "=l"(r) : "r"(lo), "r"(hi)); return r;
}
__device__ __forceinline__ float lo32(ull v) { return __uint_as_float((unsigned)v); }
__device__ __forceinline__ float hi32(ull v) { return __uint_as_float((unsigned)(v >> 32)); }

// Compute NJ columns (j = J0..J0+NJ-1) for this thread's 4-pixel vertical quad.
template <int J0, int NJ>
__device__ __forceinline__ void compute_cols(const float* __restrict__ sbuf,
                                             int tx, int qy,
                                             ull f01, ull f23,
                                             ull* __restrict__ acc01,
                                             ull* __restrict__ acc23) {
#pragma unroll
    for (int jj = 0; jj < NJ; ++jj) {
        // column = global w offset tx+J0+jj; h window [4qy, 4qy+11], 8B aligned
        const ull* col = (const ull*)(sbuf + (tx + J0 + jj) * CST + 4 * qy);
        ull v[6];
#pragma unroll
        for (int m = 0; m < 6; ++m) v[m] = col[m];   // LDS.64, conflict-free
        ull p[11];                                   // p[k] = (h=k, h=k+1) pair
#pragma unroll
        for (int m = 0; m < 6; ++m) p[2 * m] = v[m];
#pragma unroll
        for (int m = 0; m < 5; ++m)
            p[2 * m + 1] = packu((unsigned)(v[m] >> 32), (unsigned)v[m + 1]);
#pragma unroll
        for (int i = 0; i < Ss; ++i) {
            fma2(acc01[i * NJ + jj], f01, p[i]);      // pixels (0,1): h offsets i, i+1
            fma2(acc23[i * NJ + jj], f23, p[i + 2]);  // pixels (2,3): h offsets i+2, i+3
        }
    }
}

template <int J0, int NJ>
__device__ __forceinline__ void store_out(float* __restrict__ ob,
                                          const ull* __restrict__ acc01,
                                          const ull* __restrict__ acc23,
                                          float sc) {
#pragma unroll
    for (int i = 0; i < Ss; ++i) {
#pragma unroll
        for (int jj = 0; jj < NJ; ++jj) {
            const int s = i * Ss + (J0 + jj);
            float* o = ob + (size_t)s * HW;
            const ull a = acc01[i * NJ + jj];
            const ull c = acc23[i * NJ + jj];
            o[0 * Wc] = lo32(a) * sc;
            o[1 * Wc] = hi32(a) * sc;
            o[2 * Wc] = lo32(c) * sc;
            o[3 * Wc] = hi32(c) * sc;
        }
    }
}

__global__ __launch_bounds__(256, 1)
void cost_volume_kernel(const float* __restrict__ f1,
                        const float* __restrict__ f2,
                        float* __restrict__ out) {
    // column-major f2 tile: element (h_local, c) at sf2[buf][c*CST + h_local]
    __shared__ float sf2[2][SBUF];   // 8.3 KB, double buffered

    const int tid = threadIdx.x;
    const int grp = tid >> 7;        // 0: j in [0,5)   1: j in [5,9) + loader
    const int gt  = tid & 127;
    const int tx  = gt & 31;         // w within tile
    const int qy  = gt >> 5;         // quad row (4 pixels tall), 0..3
    const int w0 = blockIdx.x * TW;
    const int h0 = blockIdx.y * TH;
    const int b  = blockIdx.z;

    // ---- loader setup (group B): 240 float4 per channel over 128 threads ----
    int lval0 = 0, lval1 = 0, lsts0 = 0, lsts1 = 0, slot1 = 0;
    size_t lsrc0 = 0, lsrc1 = 0;
    if (grp == 1) {
        int L = gt, lr = L / 10, lc = L % 10;
        int gh = h0 - Dd + lr, gw = w0 - Dd + 4 * lc;
        lval0 = ((unsigned)gh < (unsigned)Hc) && (gw >= 0) && (gw <= Wc - 4);
        lsrc0 = (((size_t)b * Cc) * Hc + (lval0 ? gh : 0)) * (size_t)Wc + (lval0 ? gw : 0);
        lsts0 = (4 * lc) * CST + lr;
        slot1 = (gt < NLOAD - 128);  // gt < 112
        if (slot1) {
            L = gt + 128; lr = L / 10; lc = L % 10;
            gh = h0 - Dd + lr; gw = w0 - Dd + 4 * lc;
            lval1 = ((unsigned)gh < (unsigned)Hc) && (gw >= 0) && (gw <= Wc - 4);
            lsrc1 = (((size_t)b * Cc) * Hc + (lval1 ? gh : 0)) * (size_t)Wc + (lval1 ? gw : 0);
            lsts1 = (4 * lc) * CST + lr;
        }
    }
    auto ldg4 = [&](size_t src, int valid) -> float4 {
        float4 v = make_float4(0.f, 0.f, 0.f, 0.f);
        if (valid) v = *(const float4*)(f2 + src);
        return v;
    };
    auto sts4 = [&](int buf, int off, float4 v) {
        float* s = &sf2[buf][off];       // 4 consecutive columns, same row
        s[0 * CST] = v.x;
        s[1 * CST] = v.y;
        s[2 * CST] = v.z;
        s[3 * CST] = v.w;
    };

    // ---- f1: 4 vertically adjacent pixels per thread (coalesced across tx) ----
    const float* f1base = f1 + (((size_t)b * Cc) * Hc + (h0 + 4 * qy)) * (size_t)Wc
                             + (w0 + tx);
    float f1q[4];
#pragma unroll
    for (int p = 0; p < 4; ++p) f1q[p] = f1base[p * Wc];

    // ---- accumulators: 45 float2 pairs (A uses all, B uses 36) ----
    ull acc01[45], acc23[45];
#pragma unroll
    for (int s = 0; s < 45; ++s) { acc01[s] = 0ull; acc23[s] = 0ull; }

    // ---- prologue: stage ch0 into buf0, prefetch ch1 into regs ----
    float4 g0 = make_float4(0, 0, 0, 0), g1 = make_float4(0, 0, 0, 0);
    if (grp == 1) {
        float4 a0 = ldg4(lsrc0, lval0);
        float4 a1 = slot1 ? ldg4(lsrc1, lval1) : make_float4(0, 0, 0, 0);
        sts4(0, lsts0, a0);
        if (slot1) sts4(0, lsts1, a1);
        g0 = ldg4(lsrc0 + HW, lval0);
        if (slot1) g1 = ldg4(lsrc1 + HW, lval1);
    }
    __syncthreads();

#pragma unroll 1
    for (int ch = 0; ch < Cc; ++ch) {
        const int buf = ch & 1;

        // stage ch+1 into buf^1 (its previous readers finished at last barrier)
        if (grp == 1 && ch + 1 < Cc) {
            sts4(buf ^ 1, lsts0, g0);
            if (slot1) sts4(buf ^ 1, lsts1, g1);
        }
        // prefetch ch+2 into regs (latency hidden behind compute)
        if (grp == 1 && ch + 2 < Cc) {
            g0 = ldg4(lsrc0 + (size_t)(ch + 2) * HW, lval0);
            if (slot1) g1 = ldg4(lsrc1 + (size_t)(ch + 2) * HW, lval1);
        }
        // prefetch next channel's f1 quad
        float f1n[4] = {0.f, 0.f, 0.f, 0.f};
        if (ch + 1 < Cc) {
            const float* p = f1base + (size_t)(ch + 1) * HW;
#pragma unroll
            for (int k = 0; k < 4; ++k) f1n[k] = p[k * Wc];
        }

        const ull f01 = packf(f1q[0], f1q[1]);
        const ull f23 = packf(f1q[2], f1q[3]);
        if (grp == 0)
            compute_cols<0, 5>(sf2[buf], tx, qy, f01, f23, acc01, acc23);
        else
            compute_cols<5, 4>(sf2[buf], tx, qy, f01, f23, acc01, acc23);

#pragma unroll
        for (int k = 0; k < 4; ++k) f1q[k] = f1n[k];
        __syncthreads();
    }

    // ---- epilogue: scaled stores, coalesced across tx ----
    const float sc = 1.0f / (float)Cc;
    float* ob = out + (((size_t)b * NS) * Hc + (h0 + 4 * qy)) * (size_t)Wc + (w0 + tx);
    if (grp == 0)
        store_out<0, 5>(ob, acc01, acc23, sc);
    else
        store_out<5, 4>(ob, acc01, acc23, sc);
}

extern "C" void kernel_launch(void* const* d_in, const int* in_sizes, int n_in,
                              void* d_out, int out_size) {
    const float* f1 = (const float*)d_in[0];
    const float* f2 = (const float*)d_in[1];
    float* out = (float*)d_out;
    dim3 grid(Wc / TW, Hc / TH, Bc);   // 8 x 8 x 8 = 512 blocks
    cost_volume_kernel<<<grid, 256>>>(f1, f2, out);
}

// round 5
// speedup vs baseline: 2.4242x; 2.4242x over previous
#include <cuda_runtime.h>
#include <cstdint>

// Cost volume, B=8 C=128 H=128 W=256, d=4 -> 81 shifts.
// out[b, i*9+j, h, w] = (1/C) * sum_c f1[b,c,h,w] * f2[b,c,h+i-4,w+j-4] (zero pad)
//
// v4: 4 w-pixels per thread (12-float window -> 36 FMAs per LDS row),
// i-shifts split 3 ways across a 384-thread block, f1+f2 staged via a
// 3-stage cp.async pipeline, all smem reads LDS.128 conflict-free.

namespace {
constexpr int Bc = 8;
constexpr int Cc = 128;
constexpr int Hc = 128;
constexpr int Wc = 256;
constexpr int Dd = 4;
constexpr int Ss = 9;
constexpr int NS = 81;
constexpr int TH = 16;
constexpr int TW = 32;
constexpr int F2H = TH + 2 * Dd;    // 24
constexpr int F2W = TW + 2 * Dd;    // 40 floats row stride (16B multiple)
constexpr int HW = Hc * Wc;
constexpr int NF2 = F2H * (F2W / 4);   // 240 float4 chunks per channel
constexpr int NF1 = TH * TW / 4;       // 128 float4 chunks per channel
constexpr int NT = 384;
}

__global__ __launch_bounds__(NT, 1)
void cost_volume_kernel(const float* __restrict__ f1,
                        const float* __restrict__ f2,
                        float* __restrict__ out) {
    __shared__ __align__(16) float sf2[3][F2H * F2W];  // 11.25 KB
    __shared__ __align__(16) float sf1[3][TH * TW];    // 6 KB

    const int tid = threadIdx.x;
    const int grp = tid / 128;          // i-group: handles i = 3*grp + ii
    const int gt  = tid % 128;
    const int tx  = gt & 7;             // quad column (w = w0 + 4*tx + p)
    const int r   = gt >> 3;            // output row within tile, 0..15
    const int w0 = blockIdx.x * TW;
    const int h0 = blockIdx.y * TH;
    const int b  = blockIdx.z;

    // ---- loader roles: tid<240 -> f2 chunks, 240..367 -> f1 chunks ----
    const bool isF2 = (tid < NF2);
    const bool isF1 = (tid >= NF2) && (tid < NF2 + NF1);
    size_t src = 0; int sts = 0, srcsz = 16;
    if (isF2) {
        const int lr = tid / 10, lc = tid % 10;
        const int gh = h0 - Dd + lr;
        const int gw = w0 - Dd + 4 * lc;          // 4-aligned; halo chunks fully in/out
        const bool valid = ((unsigned)gh < (unsigned)Hc) &&
                           ((unsigned)gw < (unsigned)Wc);
        src   = (((size_t)b * Cc) * Hc + (valid ? gh : 0)) * (size_t)Wc
              + (valid ? gw : 0);
        sts   = lr * F2W + 4 * lc;
        srcsz = valid ? 16 : 0;                   // 0 -> zero-fill (padding)
    } else if (isF1) {
        const int L = tid - NF2;
        const int lr = L / 8, lc = L % 8;
        src = (((size_t)b * Cc) * Hc + (h0 + lr)) * (size_t)Wc + (w0 + 4 * lc);
        sts = lr * TW + 4 * lc;
    }

    auto issue = [&](int ch, int buf) {
        if (isF2) {
            uint32_t d = (uint32_t)__cvta_generic_to_shared(&sf2[buf][sts]);
            asm volatile("cp.async.cg.shared.global [%0], [%1], 16, %2;"
                         :: "r"(d), "l"(f2 + src + (size_t)ch * HW), "r"(srcsz));
        } else if (isF1) {
            uint32_t d = (uint32_t)__cvta_generic_to_shared(&sf1[buf][sts]);
            asm volatile("cp.async.cg.shared.global [%0], [%1], 16;"
                         :: "r"(d), "l"(f1 + src + (size_t)ch * HW));
        }
    };

    // ---- prologue: stage channels 0 and 1 ----
    issue(0, 0);
    asm volatile("cp.async.commit_group;" ::: "memory");
    issue(1, 1);
    asm volatile("cp.async.commit_group;" ::: "memory");

    // 108 accumulators: acc[ii*36 + j*4 + p], ii in [0,3), j in [0,9), p in [0,4)
    float acc[108];
#pragma unroll
    for (int s = 0; s < 108; ++s) acc[s] = 0.0f;

#pragma unroll 1
    for (int ch = 0; ch < Cc; ++ch) {
        asm volatile("cp.async.wait_group 1;" ::: "memory");
        __syncthreads();

        // stage ch+2 into buffer (ch+2)%3 (its readers finished before the barrier)
        if (ch + 2 < Cc) issue(ch + 2, (ch + 2) % 3);
        asm volatile("cp.async.commit_group;" ::: "memory");

        const int buf = ch % 3;
        const float4 f1v = *(const float4*)&sf1[buf][r * TW + 4 * tx];  // LDS.128

#pragma unroll
        for (int ii = 0; ii < 3; ++ii) {
            // shift row i = 3*grp + ii; smem f2 row = r + i
            const float* wr = &sf2[buf][(r + 3 * grp + ii) * F2W + 4 * tx];
            float w[12];
            *(float4*)&w[0] = *(const float4*)(wr);        // LDS.128, conflict-free
            *(float4*)&w[4] = *(const float4*)(wr + 4);
            *(float4*)&w[8] = *(const float4*)(wr + 8);
#pragma unroll
            for (int j = 0; j < Ss; ++j) {
                acc[ii * 36 + j * 4 + 0] = fmaf(f1v.x, w[j + 0], acc[ii * 36 + j * 4 + 0]);
                acc[ii * 36 + j * 4 + 1] = fmaf(f1v.y, w[j + 1], acc[ii * 36 + j * 4 + 1]);
                acc[ii * 36 + j * 4 + 2] = fmaf(f1v.z, w[j + 2], acc[ii * 36 + j * 4 + 2]);
                acc[ii * 36 + j * 4 + 3] = fmaf(f1v.w, w[j + 3], acc[ii * 36 + j * 4 + 3]);
            }
        }
    }

    // ---- epilogue: 27 float4 stores per thread, coalesced ----
    const float sc = 1.0f / (float)Cc;
    float* ob = out + (((size_t)b * NS) * Hc + (h0 + r)) * (size_t)Wc + (w0 + 4 * tx);
#pragma unroll
    for (int ii = 0; ii < 3; ++ii) {
#pragma unroll
        for (int j = 0; j < Ss; ++j) {
            const int s = (3 * grp + ii) * Ss + j;
            float4 v;
            v.x = acc[ii * 36 + j * 4 + 0] * sc;
            v.y = acc[ii * 36 + j * 4 + 1] * sc;
            v.z = acc[ii * 36 + j * 4 + 2] * sc;
            v.w = acc[ii * 36 + j * 4 + 3] * sc;
            *(float4*)(ob + (size_t)s * HW) = v;
        }
    }
}

extern "C" void kernel_launch(void* const* d_in, const int* in_sizes, int n_in,
                              void* d_out, int out_size) {
    const float* f1 = (const float*)d_in[0];
    const float* f2 = (const float*)d_in[1];
    float* out = (float*)d_out;
    dim3 grid(Wc / TW, Hc / TH, Bc);   // 8 x 8 x 8 = 512 blocks
    cost_volume_kernel<<<grid, NT>>>(f1, f2, out);
}